// round 12
// baseline (speedup 1.0000x reference)
#include <cuda_runtime.h>
#include <cstdint>

#define D_DIM   128
#define BM      128
#define BN      256
#define TPB     256
#define XSTR    132   // floats/row of x tile (128 data + 4 pad, 16B-aligned)
#define ESTR    260   // floats/row of e tile (256 data + 4 pad, 16B-aligned)

typedef unsigned long long u64;

__device__ __forceinline__ void fma2(u64 &d, u64 a, u64 b){
    asm("fma.rn.f32x2 %0, %1, %2, %0;" : "+l"(d) : "l"(a), "l"(b));
}
__device__ __forceinline__ void unpack2(u64 v, float &lo, float &hi){
    asm("mov.b64 {%0, %1}, %2;" : "=f"(lo), "=f"(hi) : "l"(v));
}
__device__ __forceinline__ u64 packdup(float a){
    u64 r; asm("mov.b64 %0, {%1, %1};" : "=l"(r) : "f"(a)); return r;
}

__global__ __launch_bounds__(TPB, 1)
void vq_kernel(const float* __restrict__ x, const float* __restrict__ embed,
               float* __restrict__ outInd, float* __restrict__ outQ, int K)
{
    extern __shared__ float smem[];
    float* xs   = smem;                      // [D_DIM][XSTR] transposed x tile
    float* es   = xs + D_DIM * XSTR;         // [D_DIM][ESTR] transposed e tile (256 cols)
    float* xn   = es + D_DIM * ESTR;         // [BM] row norms
    float* en   = xn + BM;                   // [BN] code norms
    int*   sIdx = (int*)(en + BN);           // [BM] winning code per row

    const int t    = threadIdx.x;
    const int lane = t & 31, warp = t >> 5;   // 8 warps
    const int tx   = t & 15, ty   = t >> 4;   // tx: col group (16 cols), ty: 8-row group
    const int m0   = blockIdx.x * BM;

    // ---- load x tile transposed + row norms ----
    for (int r = warp; r < BM; r += 8){
        const float* xr = x + (size_t)(m0 + r) * D_DIM;
        float v0 = xr[lane], v1 = xr[lane+32], v2 = xr[lane+64], v3 = xr[lane+96];
        xs[(size_t)(lane     )*XSTR + r] = v0;
        xs[(size_t)(lane + 32)*XSTR + r] = v1;
        xs[(size_t)(lane + 64)*XSTR + r] = v2;
        xs[(size_t)(lane + 96)*XSTR + r] = v3;
        float sq = v0*v0 + v1*v1 + v2*v2 + v3*v3;
        #pragma unroll
        for (int off = 16; off; off >>= 1) sq += __shfl_xor_sync(0xFFFFFFFFu, sq, off);
        if (lane == 0) xn[r] = sq;
    }

    const float NEGINF = __int_as_float(0xff800000);
    float runv[8]; int runi[8];
    #pragma unroll
    for (int i = 0; i < 8; i++){ runv[i] = NEGINF; runi[i] = 0; }

    for (int n0 = 0; n0 < K; n0 += BN){
        __syncthreads();   // previous tile's compute done reading es
        // ---- load e tile (256 codes) transposed + code norms ----
        for (int r = warp; r < BN; r += 8){
            const float* er = embed + (size_t)(n0 + r) * D_DIM;
            float v0 = er[lane], v1 = er[lane+32], v2 = er[lane+64], v3 = er[lane+96];
            es[(size_t)(lane     )*ESTR + r] = v0;
            es[(size_t)(lane + 32)*ESTR + r] = v1;
            es[(size_t)(lane + 64)*ESTR + r] = v2;
            es[(size_t)(lane + 96)*ESTR + r] = v3;
            float sq = v0*v0 + v1*v1 + v2*v2 + v3*v3;
            #pragma unroll
            for (int off = 16; off; off >>= 1) sq += __shfl_xor_sync(0xFFFFFFFFu, sq, off);
            if (lane == 0) en[r] = sq;
        }
        __syncthreads();

        // ---- 128x256 score tile: 8 rows x 16 cols per thread ----
        // cols in 4 conflict-free groups: g*64 + tx*4 .. +3  (16B lane stride)
        u64 acc[8][8];
        #pragma unroll
        for (int i = 0; i < 8; i++)
            #pragma unroll
            for (int j = 0; j < 8; j++) acc[i][j] = 0ull;

        const float* xa = xs + ty * 8;    // rows [8ty, 8ty+8)
        const float* eb = es + tx * 4;    // col groups at +0, +64, +128, +192
        #pragma unroll 4
        for (int k = 0; k < D_DIM; k++){
            float4 ar0 = *(const float4*)(xa     + (size_t)k * XSTR);
            float4 ar1 = *(const float4*)(xa + 4 + (size_t)k * XSTR);
            ulonglong2 b0 = *(const ulonglong2*)(eb       + (size_t)k * ESTR);
            ulonglong2 b1 = *(const ulonglong2*)(eb +  64 + (size_t)k * ESTR);
            ulonglong2 b2 = *(const ulonglong2*)(eb + 128 + (size_t)k * ESTR);
            ulonglong2 b3 = *(const ulonglong2*)(eb + 192 + (size_t)k * ESTR);
            u64 a[8] = { packdup(ar0.x), packdup(ar0.y), packdup(ar0.z), packdup(ar0.w),
                         packdup(ar1.x), packdup(ar1.y), packdup(ar1.z), packdup(ar1.w) };
            #pragma unroll
            for (int i = 0; i < 8; i++){
                fma2(acc[i][0], a[i], b0.x);
                fma2(acc[i][1], a[i], b0.y);
                fma2(acc[i][2], a[i], b1.x);
                fma2(acc[i][3], a[i], b1.y);
                fma2(acc[i][4], a[i], b2.x);
                fma2(acc[i][5], a[i], b2.y);
                fma2(acc[i][6], a[i], b3.x);
                fma2(acc[i][7], a[i], b3.y);
            }
        }

        // ---- epilogue: score + per-row argmax (first-occurrence tie-break) ----
        float env[8][2];
        #pragma unroll
        for (int g = 0; g < 4; g++){
            float4 e4 = *(const float4*)(en + g * 64 + tx * 4);
            env[2*g  ][0] = e4.x; env[2*g  ][1] = e4.y;
            env[2*g+1][0] = e4.z; env[2*g+1][1] = e4.w;
        }
        #pragma unroll
        for (int i = 0; i < 8; i++){
            int r = ty * 8 + i;
            float xnr = xn[r];
            float bv = NEGINF; int bi = 0;
            #pragma unroll
            for (int j = 0; j < 8; j++){
                float s0, s1; unpack2(acc[i][j], s0, s1);
                float sc0 = (2.0f * s0 - xnr) - env[j][0];
                float sc1 = (2.0f * s1 - xnr) - env[j][1];
                int c0 = n0 + (j >> 1) * 64 + tx * 4 + (j & 1) * 2;
                int c1 = c0 + 1;
                if (sc0 > bv || (sc0 == bv && c0 < bi)) { bv = sc0; bi = c0; }
                if (sc1 > bv || (sc1 == bv && c1 < bi)) { bv = sc1; bi = c1; }
            }
            // butterfly over the 16 lanes (same ty) sharing this row
            #pragma unroll
            for (int off = 8; off; off >>= 1){
                float ov = __shfl_xor_sync(0xFFFFFFFFu, bv, off);
                int   oi = __shfl_xor_sync(0xFFFFFFFFu, bi, off);
                if (ov > bv || (ov == bv && oi < bi)) { bv = ov; bi = oi; }
            }
            // earlier tiles have smaller indices: strict > keeps first occurrence
            if (bv > runv[i] || (bv == runv[i] && bi < runi[i])) { runv[i] = bv; runi[i] = bi; }
        }
    }

    // ---- write indices (as float) + stash for dequant ----
    if (tx == 0){
        #pragma unroll
        for (int i = 0; i < 8; i++){
            int r = ty * 8 + i;
            sIdx[r] = runi[i];
            outInd[m0 + r] = (float)runi[i];
        }
    }
    __syncthreads();

    // ---- dequantize: quantize[row] = embed[ind[row]] (L2-resident gather) ----
    for (int i = t; i < BM * 32; i += TPB){
        int r = i >> 5, c = i & 31;
        int code = sIdx[r];
        float4 v = *(const float4*)(embed + (size_t)code * D_DIM + c * 4);
        *(float4*)(outQ + (size_t)(m0 + r) * D_DIM + c * 4) = v;
    }
}

extern "C" void kernel_launch(void* const* d_in, const int* in_sizes, int n_in,
                              void* d_out, int out_size)
{
    const float* x     = (const float*)d_in[0];
    const float* embed = (const float*)d_in[1];
    float* out = (float*)d_out;

    int N = in_sizes[0] / D_DIM;   // 131072 rows
    int K = in_sizes[1] / D_DIM;   // 1024 codes

    size_t smem_bytes = (size_t)(D_DIM * XSTR + D_DIM * ESTR + BM + BN) * sizeof(float)
                      + (size_t)BM * sizeof(int);   // 202,752 B

    cudaFuncSetAttribute(vq_kernel, cudaFuncAttributeMaxDynamicSharedMemorySize,
                         (int)smem_bytes);

    // out layout: [embed_ind (N floats)] then [quantize (N*128 floats)]
    vq_kernel<<<N / BM, TPB, smem_bytes>>>(x, embed, out, out + N, K);
}

// round 15
// speedup vs baseline: 1.1210x; 1.1210x over previous
#include <cuda_runtime.h>
#include <cuda_bf16.h>
#include <cstdint>

#define D_DIM  128
#define BMC    256          // rows per CTA
#define TPB    256
#define BSTR   136          // bf16 per padded B-tile row (272 B)
#define CAP    32
#define EPS    0.125f

// ---- device globals: pre-split bf16 images of 2*embed, + code norms ----
__device__ __align__(16) uint32_t g_bh[1024 * 64];   // hi pairs [code][k/2]
__device__ __align__(16) uint32_t g_bl[1024 * 64];   // lo pairs
__device__ float g_en[1024];

// ---- smem layout ----
#define SM_BSH   0                         // 128 x 136 bf16 (34816 B)
#define SM_BLS   34816
#define SM_ENS   69632                     // 128 f32
#define SM_XNS   (SM_ENS + 512)            // 256 f32
#define SM_RMX   (SM_XNS + 1024)           // 256 u32
#define SM_CNT   (SM_RMX + 1024)           // 256 i32
#define SM_SIDX  (SM_CNT + 1024)           // 256 i32
#define SM_CAND  (SM_SIDX + 1024)          // 256*32 i32
#define SMEM_SZ  (SM_CAND + BMC * CAP * 4) // 107008 B

__device__ __forceinline__ void mma16816(float* c, const uint32_t* a,
                                         uint32_t b0, uint32_t b1){
    asm volatile(
        "mma.sync.aligned.m16n8k16.row.col.f32.bf16.bf16.f32 "
        "{%0,%1,%2,%3}, {%4,%5,%6,%7}, {%8,%9}, {%0,%1,%2,%3};"
        : "+f"(c[0]), "+f"(c[1]), "+f"(c[2]), "+f"(c[3])
        : "r"(a[0]), "r"(a[1]), "r"(a[2]), "r"(a[3]), "r"(b0), "r"(b1));
}

__device__ __forceinline__ uint32_t pack_bf16(__nv_bfloat16 lo, __nv_bfloat16 hi){
    return ((uint32_t)__bfloat16_as_ushort(hi) << 16) | __bfloat16_as_ushort(lo);
}

// running-max filter: candidate push when within EPS of the row's running max
__device__ __forceinline__ void push_cand(float s, int r, int c, float& lm,
                                          unsigned* rmx, int* cnt, int* cand){
    if (s >= lm - EPS){
        int  si = __float_as_int(s);
        unsigned e = (unsigned)si ^ ((unsigned)(si >> 31) | 0x80000000u);
        unsigned old = atomicMax(&rmx[r], e);
        unsigned mo  = old > e ? old : e;
        unsigned mmo = (mo & 0x80000000u) ? 0x80000000u : 0xFFFFFFFFu;
        lm = __int_as_float((int)(mo ^ mmo));                       // refresh mirror
        float om;
        if (old == 0u) om = -3.4e38f;                               // initial sentinel
        else {
            unsigned m2 = (old & 0x80000000u) ? 0x80000000u : 0xFFFFFFFFu;
            om = __int_as_float((int)(old ^ m2));
        }
        if (s >= om - EPS){
            int slot = atomicAdd(&cnt[r], 1);
            if (slot < CAP) cand[r * CAP + slot] = c;
        }
    }
}

// ---------------- prep kernels ----------------
__global__ void prep_embed(const float* __restrict__ embed){
    int idx  = blockIdx.x * blockDim.x + threadIdx.x;   // 65536 threads
    int code = idx >> 6;
    int kp   = (idx & 63) << 1;
    float2 e2 = *(const float2*)(embed + (size_t)code * D_DIM + kp);
    float f0 = 2.0f * e2.x, f1 = 2.0f * e2.y;
    __nv_bfloat16 h0 = __float2bfloat16(f0), h1 = __float2bfloat16(f1);
    __nv_bfloat16 l0 = __float2bfloat16(f0 - __bfloat162float(h0));
    __nv_bfloat16 l1 = __float2bfloat16(f1 - __bfloat162float(h1));
    g_bh[code * 64 + (kp >> 1)] = pack_bf16(h0, h1);
    g_bl[code * 64 + (kp >> 1)] = pack_bf16(l0, l1);
}

__global__ void prep_norm(const float* __restrict__ embed){
    int warp = threadIdx.x >> 5, lane = threadIdx.x & 31;
    int code = blockIdx.x * 8 + warp;
    const float* er = embed + (size_t)code * D_DIM;
    float v0 = er[lane], v1 = er[lane+32], v2 = er[lane+64], v3 = er[lane+96];
    float sq = v0*v0 + v1*v1 + v2*v2 + v3*v3;
    #pragma unroll
    for (int off = 16; off; off >>= 1) sq += __shfl_xor_sync(0xFFFFFFFFu, sq, off);
    if (lane == 0) g_en[code] = sq;
}

// ---------------- main kernel ----------------
__global__ __launch_bounds__(TPB, 1)
void vq_main(const float* __restrict__ x, const float* __restrict__ embed,
             float* __restrict__ outInd, float* __restrict__ outQ)
{
    extern __shared__ unsigned char sm[];
    __nv_bfloat16* bsh = (__nv_bfloat16*)(sm + SM_BSH);
    __nv_bfloat16* bls = (__nv_bfloat16*)(sm + SM_BLS);
    float*    enS  = (float*)(sm + SM_ENS);
    float*    xnS  = (float*)(sm + SM_XNS);
    unsigned* rmx  = (unsigned*)(sm + SM_RMX);
    int*      cnt  = (int*)(sm + SM_CNT);
    int*      sIdx = (int*)(sm + SM_SIDX);
    int*      cand = (int*)(sm + SM_CAND);

    const int t = threadIdx.x, lane = t & 31, w = t >> 5;
    const int g = lane >> 2, tig = lane & 3;
    const int m0 = blockIdx.x * BMC;
    const float NEGINF = __int_as_float(0xff800000);

    for (int i = t; i < BMC; i += TPB){ rmx[i] = 0u; cnt[i] = 0; }

    // ---- row norms (R7's exact reduction tree) ----
    for (int r = w; r < BMC; r += 8){
        const float* xr = x + (size_t)(m0 + r) * D_DIM;
        float v0 = xr[lane], v1 = xr[lane+32], v2 = xr[lane+64], v3 = xr[lane+96];
        float sq = v0*v0 + v1*v1 + v2*v2 + v3*v3;
        #pragma unroll
        for (int off = 16; off; off >>= 1) sq += __shfl_xor_sync(0xFFFFFFFFu, sq, off);
        if (lane == 0) xnS[r] = sq;
    }

    // ---- A fragments: 2 M-tiles x 8 ksteps, hi+lo, resident in registers ----
    uint32_t ah[2][8][4], al[2][8][4];
    {
        const int rowb = m0 + 32 * w;
        #pragma unroll
        for (int mt = 0; mt < 2; mt++)
            #pragma unroll
            for (int k = 0; k < 8; k++)
                #pragma unroll
                for (int i = 0; i < 4; i++){
                    int r = rowb + mt * 16 + g + ((i & 1) << 3);
                    int c = k * 16 + 2 * tig + ((i >> 1) << 3);
                    float2 v = *(const float2*)(x + (size_t)r * D_DIM + c);
                    __nv_bfloat16 h0 = __float2bfloat16(v.x);
                    __nv_bfloat16 h1 = __float2bfloat16(v.y);
                    __nv_bfloat16 l0 = __float2bfloat16(v.x - __bfloat162float(h0));
                    __nv_bfloat16 l1 = __float2bfloat16(v.y - __bfloat162float(h1));
                    ah[mt][k][i] = pack_bf16(h0, h1);
                    al[mt][k][i] = pack_bf16(l0, l1);
                }
    }

    float lm[4] = {NEGINF, NEGINF, NEGINF, NEGINF};

    for (int tl = 0; tl < 8; tl++){
        __syncthreads();
        // ---- stage B tile (128 codes, hi+lo) into padded smem ----
        {
            int arr = t >> 7, row = t & 127;
            const float4* src = (const float4*)((arr ? g_bl : g_bh) + (tl * 128 + row) * 64);
            float4* dst = (float4*)((arr ? bls : bsh) + (size_t)row * BSTR);
            #pragma unroll
            for (int i = 0; i < 16; i++) dst[i] = src[i];
            if (t < 128) enS[t] = g_en[tl * 128 + t];
        }
        __syncthreads();

        for (int nt = 0; nt < 16; nt++){
            float a0[4] = {0,0,0,0}, a1[4] = {0,0,0,0};
            const __nv_bfloat16* bp = bsh + (size_t)(nt * 8 + g) * BSTR + 2 * tig;
            const __nv_bfloat16* lp = bls + (size_t)(nt * 8 + g) * BSTR + 2 * tig;
            #pragma unroll
            for (int k = 0; k < 8; k++){
                uint32_t bh0 = *(const uint32_t*)(bp + k * 16);
                uint32_t bh1 = *(const uint32_t*)(bp + k * 16 + 8);
                uint32_t bl0 = *(const uint32_t*)(lp + k * 16);
                uint32_t bl1 = *(const uint32_t*)(lp + k * 16 + 8);
                mma16816(a0, ah[0][k], bh0, bh1);
                mma16816(a0, al[0][k], bh0, bh1);
                mma16816(a0, ah[0][k], bl0, bl1);
                mma16816(a1, ah[1][k], bh0, bh1);
                mma16816(a1, al[1][k], bh0, bh1);
                mma16816(a1, ah[1][k], bl0, bl1);
            }
            // ---- filter epilogue: approx score = D - en ----
            int c0 = tl * 128 + nt * 8 + 2 * tig;
            float2 e2 = *(const float2*)(enS + nt * 8 + 2 * tig);
            int r0 = 32 * w + g;
            push_cand(a0[0] - e2.x, r0,      c0,     lm[0], rmx, cnt, cand);
            push_cand(a0[1] - e2.y, r0,      c0 + 1, lm[0], rmx, cnt, cand);
            push_cand(a0[2] - e2.x, r0 + 8,  c0,     lm[1], rmx, cnt, cand);
            push_cand(a0[3] - e2.y, r0 + 8,  c0 + 1, lm[1], rmx, cnt, cand);
            push_cand(a1[0] - e2.x, r0 + 16, c0,     lm[2], rmx, cnt, cand);
            push_cand(a1[1] - e2.y, r0 + 16, c0 + 1, lm[2], rmx, cnt, cand);
            push_cand(a1[2] - e2.x, r0 + 24, c0,     lm[3], rmx, cnt, cand);
            push_cand(a1[3] - e2.y, r0 + 24, c0 + 1, lm[3], rmx, cnt, cand);
        }
    }
    __syncthreads();

    // ---- exact fp32 rescore (bit-identical to proven R7 math) ----
    {
        int r = t;
        float xnr = xnS[r];
        const float4* xr4 = (const float4*)(x + (size_t)(m0 + r) * D_DIM);
        float best = NEGINF; int bi = 0;
        int n = cnt[r];
        if (n <= CAP){
            for (int ci = 0; ci < n; ci++){
                int c = cand[r * CAP + ci];
                const float4* er4 = (const float4*)(embed + (size_t)c * D_DIM);
                float acc = 0.0f;
                #pragma unroll 8
                for (int i = 0; i < 32; i++){       // strict k-ascending FMA chain
                    float4 a = xr4[i], b = er4[i];
                    acc = fmaf(a.x, b.x, acc);
                    acc = fmaf(a.y, b.y, acc);
                    acc = fmaf(a.z, b.z, acc);
                    acc = fmaf(a.w, b.w, acc);
                }
                float sc = (2.0f * acc - xnr) - g_en[c];
                if (sc > best || (sc == best && c < bi)) { best = sc; bi = c; }
            }
        } else {
            // overflow fallback: exact full scan (correct, astronomically rare)
            for (int c = 0; c < 1024; c++){
                const float4* er4 = (const float4*)(embed + (size_t)c * D_DIM);
                float acc = 0.0f;
                #pragma unroll 8
                for (int i = 0; i < 32; i++){
                    float4 a = xr4[i], b = er4[i];
                    acc = fmaf(a.x, b.x, acc);
                    acc = fmaf(a.y, b.y, acc);
                    acc = fmaf(a.z, b.z, acc);
                    acc = fmaf(a.w, b.w, acc);
                }
                float sc = (2.0f * acc - xnr) - g_en[c];
                if (sc > best) { best = sc; bi = c; }   // ascending c: > keeps first
            }
        }
        sIdx[r] = bi;
        outInd[m0 + r] = (float)bi;
    }
    __syncthreads();

    // ---- dequantize: quantize[row] = embed[ind[row]] ----
    for (int i = t; i < BMC * 32; i += TPB){
        int r = i >> 5, c = i & 31;
        int code = sIdx[r];
        float4 v = *(const float4*)(embed + (size_t)code * D_DIM + c * 4);
        *(float4*)(outQ + (size_t)(m0 + r) * D_DIM + c * 4) = v;
    }
}

extern "C" void kernel_launch(void* const* d_in, const int* in_sizes, int n_in,
                              void* d_out, int out_size)
{
    const float* x     = (const float*)d_in[0];
    const float* embed = (const float*)d_in[1];
    float* out = (float*)d_out;

    int N = in_sizes[0] / D_DIM;   // 131072 rows

    cudaFuncSetAttribute(vq_main, cudaFuncAttributeMaxDynamicSharedMemorySize, SMEM_SZ);

    prep_embed<<<256, 256>>>(embed);   // bf16 hi/lo split of 2*embed
    prep_norm<<<128, 256>>>(embed);    // code norms (R7 reduction tree)
    // out layout: [embed_ind (N floats)] then [quantize (N*128 floats)]
    vq_main<<<N / BMC, TPB, SMEM_SZ>>>(x, embed, out, out + N);
}